// round 15
// baseline (speedup 1.0000x reference)
#include <cuda_runtime.h>
#include <cuda_fp16.h>
#include <math.h>
#include <stdint.h>

// ---------------- problem constants ----------------
#define Bb 2
#define Ss 2048
#define Dd 512
#define NLAYERS 6
#define DI 1024
#define Hh 8
#define Nn 16
#define Kk 4
#define Vv 32000
#define TOT (2*DI + Hh + 2*Hh*Nn)   // 2312
#define ROWS (Bb*Ss)                // 4096

// weight pool offsets (halves)
#define WOFF_IN   0
#define WOFF_OUT  (NLAYERS*TOT*Dd)
#define WOFF_HEAD (WOFF_OUT + NLAYERS*Dd*DI)
#define WPOOL     (WOFF_HEAD + (size_t)Vv*Dd)

// ---------------- scratch (static device globals; no allocation) ----------------
__device__ float g_x [ROWS*Dd];
__device__ float g_p [ROWS*TOT];
__device__ float g_dt[ROWS*Hh];
__device__ float g_xin[ROWS*Hh];
__device__ float g_hs[ROWS*Hh*Nn];
__device__ float g_y [ROWS*Hh];
__device__ __align__(128) __half g_af16[ROWS*DI];
__device__ __align__(128) __half g_wf16[WPOOL];

// ---------------- small helpers ----------------
__device__ __forceinline__ float blockReduceSum256(float v, float* sh) {
    int t = threadIdx.x;
    sh[t] = v; __syncthreads();
    #pragma unroll
    for (int o = 128; o > 0; o >>= 1) {
        if (t < o) sh[t] += sh[t + o];
        __syncthreads();
    }
    float r = sh[0];
    __syncthreads();
    return r;
}
__device__ __forceinline__ float siluf(float v) { return v / (1.f + expf(-v)); }
__device__ __forceinline__ float softplusf(float v) {
    return (v > 0.f) ? (v + log1pf(expf(-v))) : log1pf(expf(v));
}

// ---------------- MMA primitives (arch-neutral, sm_80+) ----------------
__device__ __forceinline__ void cp16(uint32_t s, const void* g, uint32_t sz) {
    asm volatile("cp.async.cg.shared.global [%0], [%1], 16, %2;"
                 :: "r"(s), "l"(g), "r"(sz) : "memory");
}
__device__ __forceinline__ void cp_commit() {
    asm volatile("cp.async.commit_group;" ::: "memory");
}
__device__ __forceinline__ void cp_wait1() {
    asm volatile("cp.async.wait_group 1;" ::: "memory");
}
__device__ __forceinline__ void ldm4(uint32_t* r, uint32_t a) {
    asm volatile("ldmatrix.sync.aligned.m8n8.x4.shared.b16 {%0,%1,%2,%3}, [%4];"
                 : "=r"(r[0]), "=r"(r[1]), "=r"(r[2]), "=r"(r[3]) : "r"(a));
}
__device__ __forceinline__ void mma16816(float* d, const uint32_t* a,
                                         uint32_t b0, uint32_t b1) {
    asm volatile("mma.sync.aligned.m16n8k16.row.col.f32.f16.f16.f32 "
                 "{%0,%1,%2,%3}, {%4,%5,%6,%7}, {%8,%9}, {%0,%1,%2,%3};"
                 : "+f"(d[0]), "+f"(d[1]), "+f"(d[2]), "+f"(d[3])
                 : "r"(a[0]), "r"(a[1]), "r"(a[2]), "r"(a[3]), "r"(b0), "r"(b1));
}

// ---------------- fp32 -> fp16 weight convert ----------------
__global__ void k_wcvt(const float* __restrict__ src, __half* __restrict__ dst, int n) {
    int i = (blockIdx.x * blockDim.x + threadIdx.x) * 4;
    if (i >= n) return;
    float4 v = *(const float4*)(src + i);
    ((__half2*)(dst + i))[0] = __floats2half2_rn(v.x, v.y);
    ((__half2*)(dst + i))[1] = __floats2half2_rn(v.z, v.w);
}

// ---------------- FP16 GEMM: C[M,N] = A[M,K] @ B[N,K]^T (+res)(+bias) ----------------
// MW = warps along M (2 -> BM=128, 256 thr; 4 -> BM=256, 512 thr). BN=128, BK=64.
// 3-stage cp.async pipeline, one barrier per chunk. R13-proven inner loop
// (B fragments held per k-step, A streamed; no register double-buffering).
#define HSTRIDE 144                    // bytes per smem row (128 data + 16 pad)
#define BTILE_H (128*HSTRIDE)          // 18432

template<int MW, int ADD_RES, int ADD_BIAS>
__global__ void __launch_bounds__(MW*128, MW == 2 ? 2 : 1)
k_gemm_fp16(const __half* __restrict__ A, const __half* __restrict__ B,
            const float* __restrict__ Res, const float* __restrict__ bias,
            float* __restrict__ C, int Nd, int Kd)
{
    constexpr int THREADS = MW * 128;
    constexpr int BM = MW * 64;
    constexpr int ATILE = BM * HSTRIDE;
    constexpr int STAGE = ATILE + BTILE_H;

    extern __shared__ char smem[];
    const uint32_t sbase = (uint32_t)__cvta_generic_to_shared(smem);

    int tid = threadIdx.x, wid = tid >> 5, lane = tid & 31;
    int bm = blockIdx.y * BM, bn = blockIdx.x * 128;
    int wm = (wid >> 2) * 64, wn = (wid & 3) * 32;

    float acc[4][4][4];
    #pragma unroll
    for (int i = 0; i < 4; i++)
        #pragma unroll
        for (int j = 0; j < 4; j++)
            #pragma unroll
            for (int q = 0; q < 4; q++) acc[i][j][q] = 0.f;

    const int nch = Kd >> 6;

    auto load_stage = [&](int slot, int ch) {
        uint32_t sb = sbase + slot * STAGE;
        int k0 = ch << 6;
        // A: BM rows x 8 chunks of 16B
        #pragma unroll
        for (int j = 0; j < 4; j++) {
            int c = tid + j * THREADS;
            int row = c >> 3, q = c & 7;
            uint32_t so = (uint32_t)(row * HSTRIDE + q * 16);
            size_t ga = (size_t)(bm + row) * Kd + k0 + q * 8;
            cp16(sb + so, A + ga, 16);
        }
        // B: 128 rows x 8 chunks
        #pragma unroll
        for (int j = 0; j < 8 / MW; j++) {
            int c = tid + j * THREADS;
            int row = c >> 3, q = c & 7;
            uint32_t so = (uint32_t)(row * HSTRIDE + q * 16);
            int brow = bn + row;
            uint32_t sz = (brow < Nd) ? 16u : 0u;
            int brc = brow < Nd ? brow : (Nd - 1);
            size_t gb = (size_t)brc * Kd + k0 + q * 8;
            cp16(sb + ATILE + so, B + gb, sz);
        }
        cp_commit();
    };

    load_stage(0, 0);
    if (nch > 1) load_stage(1, 1); else cp_commit();

    for (int ch = 0; ch < nch; ch++) {
        cp_wait1();
        __syncthreads();
        if (ch + 2 < nch) load_stage((ch + 2) % 3, ch + 2);
        else              cp_commit();

        uint32_t sb = sbase + (ch % 3) * STAGE;
        uint32_t sA = sb, sB = sb + ATILE;

        #pragma unroll
        for (int ks = 0; ks < 4; ks++) {
            // B fragments for both n16 subtiles (held across mt loop)
            uint32_t bF[2][4];
            int brow = ((lane & 16) ? 8 : 0) + (lane & 7);
            int bcb  = ks * 32 + ((lane & 8) ? 16 : 0);
            #pragma unroll
            for (int ntp = 0; ntp < 2; ntp++) {
                uint32_t bo = (uint32_t)((wn + ntp*16 + brow) * HSTRIDE + bcb);
                ldm4(bF[ntp], sB + bo);
            }
            // stream A fragments per 16-row subtile
            int arow = (lane & 15);
            int acb  = ks * 32 + ((lane & 16) ? 16 : 0);
            #pragma unroll
            for (int mt = 0; mt < 4; mt++) {
                uint32_t aF[4];
                uint32_t ao = (uint32_t)((wm + mt*16 + arow) * HSTRIDE + acb);
                ldm4(aF, sA + ao);
                #pragma unroll
                for (int ntp = 0; ntp < 2; ntp++) {
                    int nt0 = ntp * 2;
                    mma16816(acc[mt][nt0],   aF, bF[ntp][0], bF[ntp][1]);
                    mma16816(acc[mt][nt0+1], aF, bF[ntp][2], bF[ntp][3]);
                }
            }
        }
    }

    #pragma unroll
    for (int mt = 0; mt < 4; mt++) {
        int r0 = bm + wm + mt*16 + (lane >> 2);
        #pragma unroll
        for (int nt = 0; nt < 4; nt++) {
            int n = bn + wn + nt*8 + (lane & 3) * 2;
            if (n < Nd) {
                float2 v0 = make_float2(acc[mt][nt][0], acc[mt][nt][1]);
                float2 v1 = make_float2(acc[mt][nt][2], acc[mt][nt][3]);
                if (ADD_BIAS) {
                    float2 bv = *(const float2*)(bias + n);
                    v0.x += bv.x; v0.y += bv.y; v1.x += bv.x; v1.y += bv.y;
                }
                if (ADD_RES) {
                    float2 r0v = *(const float2*)(Res + (size_t)r0 * Nd + n);
                    float2 r1v = *(const float2*)(Res + (size_t)(r0+8) * Nd + n);
                    v0.x += r0v.x; v0.y += r0v.y; v1.x += r1v.x; v1.y += r1v.y;
                }
                *(float2*)(C + (size_t)r0 * Nd + n)     = v0;
                *(float2*)(C + (size_t)(r0+8) * Nd + n) = v1;
            }
        }
    }
}

#define GEMM_SMEM2 (3*(128*HSTRIDE + BTILE_H))   // 110592
#define GEMM_SMEM4 (3*(256*HSTRIDE + BTILE_H))   // 165888

// ---------------- embedding gather ----------------
__global__ void k_embed(const int* __restrict__ tok, const float* __restrict__ emb) {
    int i = blockIdx.x * blockDim.x + threadIdx.x;
    if (i < ROWS * Dd) {
        int r = i / Dd, d = i - r * Dd;
        g_x[i] = emb[(size_t)tok[r] * Dd + d];
    }
}

// ---------------- rmsnorm -> fp16 A operand ----------------
__global__ void k_rms(const float* __restrict__ rms_w) {
    __shared__ float sh[256];
    int r = blockIdx.x, t = threadIdx.x;
    float v0 = g_x[(size_t)r*Dd + t];
    float v1 = g_x[(size_t)r*Dd + t + 256];
    float ss = blockReduceSum256(v0*v0 + v1*v1, sh);
    float sc = rsqrtf(ss / (float)Dd + 1e-6f);
    g_af16[(size_t)r*Dd + t]       = __float2half_rn(v0 * sc * rms_w[t]);
    g_af16[(size_t)r*Dd + t + 256] = __float2half_rn(v1 * sc * rms_w[t + 256]);
}

// ---------------- fused conv+SiLU+head-mean+dt-softplus ----------------
__global__ __launch_bounds__(256)
void k_convdtx(const float* __restrict__ cw, const float* __restrict__ dtb) {
    int r = blockIdx.x;
    int s = r % Ss, b = r / Ss;
    int w = threadIdx.x >> 5, lane = threadIdx.x & 31;
    float sum = 0.f;
    #pragma unroll
    for (int j = 0; j < 4; j++) {
        int c = w * 128 + lane + 32 * j;
        float4 cv = ((const float4*)cw)[c];
        float acc = 0.f;
        const float* base = &g_p[(size_t)(b*Ss) * TOT + DI + c];
        if (s >= 3) {
            acc = base[(size_t)(s-3)*TOT] * cv.x + base[(size_t)(s-2)*TOT] * cv.y
                + base[(size_t)(s-1)*TOT] * cv.z + base[(size_t)s*TOT] * cv.w;
        } else {
            #pragma unroll
            for (int k = 0; k < 4; k++) {
                int sp = s + k - 3;
                if (sp >= 0) acc += base[(size_t)sp*TOT] * ((const float*)&cv)[k];
            }
        }
        sum += siluf(acc);
    }
    #pragma unroll
    for (int o = 16; o > 0; o >>= 1) sum += __shfl_xor_sync(0xffffffffu, sum, o);
    if (lane == 0) {
        g_xin[r*Hh + w] = sum * (1.f / 128.f);
        float dt = g_p[(size_t)r*TOT + 2*DI + w] + dtb[w];
        g_dt[r*Hh + w] = softplusf(dt);
    }
}

// ---------------- parallel associative scan ----------------
__global__ __launch_bounds__(256)
void k_scan(const float* __restrict__ A_log) {
    const int CH = Ss / 256;
    int chain = blockIdx.x;
    int n = chain % Nn;
    int h = (chain / Nn) % Hh;
    int b = chain / (Nn * Hh);
    float Ah = -expf(A_log[h]);

    int t = threadIdx.x;
    float hloc[CH], cA[CH];
    float a = 1.f, hv = 0.f;
    int s0 = t * CH;
    #pragma unroll
    for (int j = 0; j < CH; j++) {
        int r = b*Ss + s0 + j;
        float dt = g_dt[r*Hh + h];
        float dA = expf(dt * Ah);
        float u  = dt * g_xin[r*Hh + h] * g_p[(size_t)r*TOT + 2*DI + Hh + h*Nn + n];
        hv = dA * hv + u;
        a *= dA;
        hloc[j] = hv; cA[j] = a;
    }
    __shared__ float sA[256], sB[256];
    sA[t] = a; sB[t] = hv;
    __syncthreads();
    for (int off = 1; off < 256; off <<= 1) {
        float pa = 0.f, pb = 0.f;
        if (t >= off) { pa = sA[t - off]; pb = sB[t - off]; }
        __syncthreads();
        if (t >= off) { sB[t] = sA[t] * pb + sB[t]; sA[t] = sA[t] * pa; }
        __syncthreads();
    }
    float hin = (t == 0) ? 0.f : sB[t - 1];
    #pragma unroll
    for (int j = 0; j < CH; j++) {
        int r = b*Ss + s0 + j;
        g_hs[((size_t)r*Hh + h) * Nn + n] = hloc[j] + cA[j] * hin;
    }
}

// ---------------- y = sum_n h*C ----------------
__global__ void k_yred() {
    int i = blockIdx.x * blockDim.x + threadIdx.x;
    if (i >= ROWS * Hh) return;
    int h = i % Hh;
    int r = i / Hh;
    const float* hs = &g_hs[(size_t)i * Nn];
    const float* Cp = &g_p[(size_t)r*TOT + 2*DI + Hh + Hh*Nn + h*Nn];
    float s = 0.f;
    #pragma unroll
    for (int n = 0; n < Nn; n++) s += hs[n] * Cp[n];
    g_y[i] = s;
}

// ---------------- y_proj + gate -> fp16 A operand ----------------
__global__ void k_ymix(const float* __restrict__ yw) {
    int i = blockIdx.x * blockDim.x + threadIdx.x;
    if (i >= ROWS * DI) return;
    int c = i % DI;
    int r = i / DI;
    float4 w0 = ((const float4*)yw)[c*2];
    float4 w1 = ((const float4*)yw)[c*2 + 1];
    const float* y = &g_y[r*Hh];
    float s = y[0]*w0.x + y[1]*w0.y + y[2]*w0.z + y[3]*w0.w
            + y[4]*w1.x + y[5]*w1.y + y[6]*w1.z + y[7]*w1.w;
    float z = g_p[(size_t)r*TOT + c];
    g_af16[i] = __float2half_rn(s * siluf(z));
}

// ---------------- final layernorm -> fp16 A operand ----------------
__global__ void k_ln(const float* __restrict__ ln_w, const float* __restrict__ ln_b) {
    __shared__ float sh[256];
    int r = blockIdx.x, t = threadIdx.x;
    float v0 = g_x[(size_t)r*Dd + t];
    float v1 = g_x[(size_t)r*Dd + t + 256];
    float mu = blockReduceSum256(v0 + v1, sh) / (float)Dd;
    float d0 = v0 - mu, d1 = v1 - mu;
    float var = blockReduceSum256(d0*d0 + d1*d1, sh) / (float)Dd;
    float sc = rsqrtf(var + 1e-5f);
    g_af16[(size_t)r*Dd + t]       = __float2half_rn(d0 * sc * ln_w[t]       + ln_b[t]);
    g_af16[(size_t)r*Dd + t + 256] = __float2half_rn(d1 * sc * ln_w[t + 256] + ln_b[t + 256]);
}

// ---------------- launch ----------------
extern "C" void kernel_launch(void* const* d_in, const int* in_sizes, int n_in,
                              void* d_out, int out_size) {
    const int*   tok    = (const int*)  d_in[0];
    const float* emb    = (const float*)d_in[1];
    const float* rms_w  = (const float*)d_in[2];
    const float* in_w   = (const float*)d_in[3];
    const float* conv_w = (const float*)d_in[4];
    const float* dt_b   = (const float*)d_in[5];
    const float* A_log  = (const float*)d_in[6];
    const float* y_w    = (const float*)d_in[7];
    const float* out_w  = (const float*)d_in[8];
    const float* ln_w   = (const float*)d_in[9];
    const float* ln_b   = (const float*)d_in[10];
    const float* head_w = (const float*)d_in[11];
    const float* head_b = (const float*)d_in[12];
    float* out = (float*)d_out;

    float *p_x, *p_p;
    cudaGetSymbolAddress((void**)&p_x, g_x);
    cudaGetSymbolAddress((void**)&p_p, g_p);
    __half *p_a, *p_w;
    cudaGetSymbolAddress((void**)&p_a, g_af16);
    cudaGetSymbolAddress((void**)&p_w, g_wf16);

    static int smem_set = 0;
    if (!smem_set) {
        cudaFuncSetAttribute(k_gemm_fp16<2,0,0>, cudaFuncAttributeMaxDynamicSharedMemorySize, GEMM_SMEM2);
        cudaFuncSetAttribute(k_gemm_fp16<2,1,0>, cudaFuncAttributeMaxDynamicSharedMemorySize, GEMM_SMEM2);
        cudaFuncSetAttribute(k_gemm_fp16<4,0,1>, cudaFuncAttributeMaxDynamicSharedMemorySize, GEMM_SMEM4);
        smem_set = 1;
    }

    // batched weight conversion (all layers + head) up front
    k_wcvt<<<(NLAYERS*TOT*Dd/4 + 255)/256, 256>>>(in_w,  p_w + WOFF_IN,  NLAYERS*TOT*Dd);
    k_wcvt<<<(NLAYERS*Dd*DI/4 + 255)/256, 256>>>(out_w, p_w + WOFF_OUT, NLAYERS*Dd*DI);
    k_wcvt<<<((int)((size_t)Vv*Dd/4) + 255)/256, 256>>>(head_w, p_w + WOFF_HEAD, Vv*Dd);

    k_embed<<<(ROWS*Dd + 255)/256, 256>>>(tok, emb);

    for (int L = 0; L < NLAYERS; L++) {
        k_rms<<<ROWS, 256>>>(rms_w + (size_t)L*Dd);

        // p = xn @ in_w^T  (M=4096, N=2312, K=512)
        {
            dim3 g((TOT + 127)/128, ROWS/128);
            k_gemm_fp16<2,0,0><<<g, 256, GEMM_SMEM2>>>(p_a, p_w + WOFF_IN + (size_t)L*TOT*Dd,
                                                       nullptr, nullptr, p_p, TOT, Dd);
        }

        k_convdtx<<<ROWS, 256>>>(conv_w + (size_t)L*DI*Kk, dt_b + (size_t)L*Hh);
        k_scan<<<Bb*Hh*Nn, 256>>>(A_log + (size_t)L*Hh);
        k_yred<<<(ROWS*Hh + 255)/256, 256>>>();
        k_ymix<<<(ROWS*DI + 255)/256, 256>>>(y_w + (size_t)L*DI*Hh);

        // x = yi @ out_w^T + x  (M=4096, N=512, K=1024)
        {
            dim3 g(Dd/128, ROWS/128);
            k_gemm_fp16<2,1,0><<<g, 256, GEMM_SMEM2>>>(p_a, p_w + WOFF_OUT + (size_t)L*Dd*DI,
                                                       p_x, nullptr, p_x, Dd, DI);
        }
    }

    k_ln<<<ROWS, 256>>>(ln_w, ln_b);

    // out = xn @ head_w^T + head_b  (M=4096, N=32000, K=512), BM=256
    {
        dim3 g(Vv/128, ROWS/256);
        k_gemm_fp16<4,0,1><<<g, 512, GEMM_SMEM4>>>(p_a, p_w + WOFF_HEAD,
                                                   nullptr, head_b, out, Vv, Dd);
    }
}

// round 16
// speedup vs baseline: 1.0644x; 1.0644x over previous
#include <cuda_runtime.h>
#include <cuda_fp16.h>
#include <math.h>
#include <stdint.h>

// ---------------- problem constants ----------------
#define Bb 2
#define Ss 2048
#define Dd 512
#define NLAYERS 6
#define DI 1024
#define Hh 8
#define Nn 16
#define Kk 4
#define Vv 32000
#define TOT (2*DI + Hh + 2*Hh*Nn)   // 2312
#define ROWS (Bb*Ss)                // 4096

// weight pool offsets (halves)
#define WOFF_IN   0
#define WOFF_OUT  (NLAYERS*TOT*Dd)
#define WOFF_HEAD (WOFF_OUT + NLAYERS*Dd*DI)
#define WPOOL     (WOFF_HEAD + (size_t)Vv*Dd)

// ---------------- scratch (static device globals; no allocation) ----------------
__device__ float g_x [ROWS*Dd];
__device__ float g_p [ROWS*TOT];
__device__ float g_dt[ROWS*Hh];
__device__ float g_xin[ROWS*Hh];
__device__ float g_hs[ROWS*Hh*Nn];
__device__ __align__(128) __half g_af16[ROWS*DI];
__device__ __align__(128) __half g_wf16[WPOOL];

// ---------------- small helpers ----------------
__device__ __forceinline__ float blockReduceSum256(float v, float* sh) {
    int t = threadIdx.x;
    sh[t] = v; __syncthreads();
    #pragma unroll
    for (int o = 128; o > 0; o >>= 1) {
        if (t < o) sh[t] += sh[t + o];
        __syncthreads();
    }
    float r = sh[0];
    __syncthreads();
    return r;
}
__device__ __forceinline__ float siluf(float v) { return v / (1.f + expf(-v)); }
__device__ __forceinline__ float softplusf(float v) {
    return (v > 0.f) ? (v + log1pf(expf(-v))) : log1pf(expf(v));
}

// ---------------- MMA primitives (arch-neutral, sm_80+) ----------------
__device__ __forceinline__ void cp16(uint32_t s, const void* g, uint32_t sz) {
    asm volatile("cp.async.cg.shared.global [%0], [%1], 16, %2;"
                 :: "r"(s), "l"(g), "r"(sz) : "memory");
}
__device__ __forceinline__ void cp_commit() {
    asm volatile("cp.async.commit_group;" ::: "memory");
}
__device__ __forceinline__ void cp_wait1() {
    asm volatile("cp.async.wait_group 1;" ::: "memory");
}
__device__ __forceinline__ void ldm4(uint32_t* r, uint32_t a) {
    asm volatile("ldmatrix.sync.aligned.m8n8.x4.shared.b16 {%0,%1,%2,%3}, [%4];"
                 : "=r"(r[0]), "=r"(r[1]), "=r"(r[2]), "=r"(r[3]) : "r"(a));
}
__device__ __forceinline__ void mma16816(float* d, const uint32_t* a,
                                         uint32_t b0, uint32_t b1) {
    asm volatile("mma.sync.aligned.m16n8k16.row.col.f32.f16.f16.f32 "
                 "{%0,%1,%2,%3}, {%4,%5,%6,%7}, {%8,%9}, {%0,%1,%2,%3};"
                 : "+f"(d[0]), "+f"(d[1]), "+f"(d[2]), "+f"(d[3])
                 : "r"(a[0]), "r"(a[1]), "r"(a[2]), "r"(a[3]), "r"(b0), "r"(b1));
}

// ---------------- fp32 -> fp16 weight convert ----------------
__global__ void k_wcvt(const float* __restrict__ src, __half* __restrict__ dst, int n) {
    int i = (blockIdx.x * blockDim.x + threadIdx.x) * 4;
    if (i >= n) return;
    float4 v = *(const float4*)(src + i);
    ((__half2*)(dst + i))[0] = __floats2half2_rn(v.x, v.y);
    ((__half2*)(dst + i))[1] = __floats2half2_rn(v.z, v.w);
}

// ---------------- FP16 GEMM: C[M,N] = A[M,K] @ B[N,K]^T (+res)(+bias) ----------------
// BM=128, BN=128, BK=64, 256 threads, 2 CTAs/SM. 3-stage cp.async pipeline,
// one barrier per chunk. R13-proven inner loop.
#define HSTRIDE 144                    // bytes per smem row (128 data + 16 pad)
#define BTILE_H (128*HSTRIDE)          // 18432
#define STAGE_H (2*BTILE_H)            // 36864
#define GEMM_SMEM (3*STAGE_H)          // 110592

template<int ADD_RES, int ADD_BIAS>
__global__ void __launch_bounds__(256, 2)
k_gemm_fp16(const __half* __restrict__ A, const __half* __restrict__ B,
            const float* __restrict__ Res, const float* __restrict__ bias,
            float* __restrict__ C, int Nd, int Kd)
{
    extern __shared__ char smem[];
    const uint32_t sbase = (uint32_t)__cvta_generic_to_shared(smem);

    int tid = threadIdx.x, wid = tid >> 5, lane = tid & 31;
    int bm = blockIdx.y * 128, bn = blockIdx.x * 128;
    int wm = (wid >> 2) * 64, wn = (wid & 3) * 32;

    float acc[4][4][4];
    #pragma unroll
    for (int i = 0; i < 4; i++)
        #pragma unroll
        for (int j = 0; j < 4; j++)
            #pragma unroll
            for (int q = 0; q < 4; q++) acc[i][j][q] = 0.f;

    const int nch = Kd >> 6;

    auto load_stage = [&](int slot, int ch) {
        uint32_t sb = sbase + slot * STAGE_H;
        int k0 = ch << 6;
        #pragma unroll
        for (int j = 0; j < 4; j++) {
            int c = tid + j * 256;
            int row = c >> 3, q = c & 7;
            uint32_t so = (uint32_t)(row * HSTRIDE + q * 16);
            size_t ga = (size_t)(bm + row) * Kd + k0 + q * 8;
            cp16(sb + so, A + ga, 16);
            int brow = bn + row;
            uint32_t sz = (brow < Nd) ? 16u : 0u;
            int brc = brow < Nd ? brow : (Nd - 1);
            size_t gb = (size_t)brc * Kd + k0 + q * 8;
            cp16(sb + BTILE_H + so, B + gb, sz);
        }
        cp_commit();
    };

    load_stage(0, 0);
    if (nch > 1) load_stage(1, 1); else cp_commit();

    for (int ch = 0; ch < nch; ch++) {
        cp_wait1();
        __syncthreads();
        if (ch + 2 < nch) load_stage((ch + 2) % 3, ch + 2);
        else              cp_commit();

        uint32_t sb = sbase + (ch % 3) * STAGE_H;
        uint32_t sA = sb, sB = sb + BTILE_H;

        #pragma unroll
        for (int ks = 0; ks < 4; ks++) {
            uint32_t bF[2][4];
            int brow = ((lane & 16) ? 8 : 0) + (lane & 7);
            int bcb  = ks * 32 + ((lane & 8) ? 16 : 0);
            #pragma unroll
            for (int ntp = 0; ntp < 2; ntp++) {
                uint32_t bo = (uint32_t)((wn + ntp*16 + brow) * HSTRIDE + bcb);
                ldm4(bF[ntp], sB + bo);
            }
            int arow = (lane & 15);
            int acb  = ks * 32 + ((lane & 16) ? 16 : 0);
            #pragma unroll
            for (int mt = 0; mt < 4; mt++) {
                uint32_t aF[4];
                uint32_t ao = (uint32_t)((wm + mt*16 + arow) * HSTRIDE + acb);
                ldm4(aF, sA + ao);
                #pragma unroll
                for (int ntp = 0; ntp < 2; ntp++) {
                    int nt0 = ntp * 2;
                    mma16816(acc[mt][nt0],   aF, bF[ntp][0], bF[ntp][1]);
                    mma16816(acc[mt][nt0+1], aF, bF[ntp][2], bF[ntp][3]);
                }
            }
        }
    }

    #pragma unroll
    for (int mt = 0; mt < 4; mt++) {
        int r0 = bm + wm + mt*16 + (lane >> 2);
        #pragma unroll
        for (int nt = 0; nt < 4; nt++) {
            int n = bn + wn + nt*8 + (lane & 3) * 2;
            if (n < Nd) {
                float2 v0 = make_float2(acc[mt][nt][0], acc[mt][nt][1]);
                float2 v1 = make_float2(acc[mt][nt][2], acc[mt][nt][3]);
                if (ADD_BIAS) {
                    float2 bv = *(const float2*)(bias + n);
                    v0.x += bv.x; v0.y += bv.y; v1.x += bv.x; v1.y += bv.y;
                }
                if (ADD_RES) {
                    float2 r0v = *(const float2*)(Res + (size_t)r0 * Nd + n);
                    float2 r1v = *(const float2*)(Res + (size_t)(r0+8) * Nd + n);
                    v0.x += r0v.x; v0.y += r0v.y; v1.x += r1v.x; v1.y += r1v.y;
                }
                *(float2*)(C + (size_t)r0 * Nd + n)     = v0;
                *(float2*)(C + (size_t)(r0+8) * Nd + n) = v1;
            }
        }
    }
}

// ---------------- embedding gather ----------------
__global__ void k_embed(const int* __restrict__ tok, const float* __restrict__ emb) {
    int i = blockIdx.x * blockDim.x + threadIdx.x;
    if (i < ROWS * Dd) {
        int r = i / Dd, d = i - r * Dd;
        g_x[i] = emb[(size_t)tok[r] * Dd + d];
    }
}

// ---------------- rmsnorm -> fp16 A operand ----------------
__global__ void k_rms(const float* __restrict__ rms_w) {
    __shared__ float sh[256];
    int r = blockIdx.x, t = threadIdx.x;
    float v0 = g_x[(size_t)r*Dd + t];
    float v1 = g_x[(size_t)r*Dd + t + 256];
    float ss = blockReduceSum256(v0*v0 + v1*v1, sh);
    float sc = rsqrtf(ss / (float)Dd + 1e-6f);
    g_af16[(size_t)r*Dd + t]       = __float2half_rn(v0 * sc * rms_w[t]);
    g_af16[(size_t)r*Dd + t + 256] = __float2half_rn(v1 * sc * rms_w[t + 256]);
}

// ---------------- fused conv+SiLU+head-mean+dt-softplus ----------------
__global__ __launch_bounds__(256)
void k_convdtx(const float* __restrict__ cw, const float* __restrict__ dtb) {
    int r = blockIdx.x;
    int s = r % Ss, b = r / Ss;
    int w = threadIdx.x >> 5, lane = threadIdx.x & 31;
    float sum = 0.f;
    #pragma unroll
    for (int j = 0; j < 4; j++) {
        int c = w * 128 + lane + 32 * j;
        float4 cv = ((const float4*)cw)[c];
        float acc = 0.f;
        const float* base = &g_p[(size_t)(b*Ss) * TOT + DI + c];
        if (s >= 3) {
            acc = base[(size_t)(s-3)*TOT] * cv.x + base[(size_t)(s-2)*TOT] * cv.y
                + base[(size_t)(s-1)*TOT] * cv.z + base[(size_t)s*TOT] * cv.w;
        } else {
            #pragma unroll
            for (int k = 0; k < 4; k++) {
                int sp = s + k - 3;
                if (sp >= 0) acc += base[(size_t)sp*TOT] * ((const float*)&cv)[k];
            }
        }
        sum += siluf(acc);
    }
    #pragma unroll
    for (int o = 16; o > 0; o >>= 1) sum += __shfl_xor_sync(0xffffffffu, sum, o);
    if (lane == 0) {
        g_xin[r*Hh + w] = sum * (1.f / 128.f);
        float dt = g_p[(size_t)r*TOT + 2*DI + w] + dtb[w];
        g_dt[r*Hh + w] = softplusf(dt);
    }
}

// ---------------- parallel associative scan ----------------
__global__ __launch_bounds__(256)
void k_scan(const float* __restrict__ A_log) {
    const int CH = Ss / 256;
    int chain = blockIdx.x;
    int n = chain % Nn;
    int h = (chain / Nn) % Hh;
    int b = chain / (Nn * Hh);
    float Ah = -expf(A_log[h]);

    int t = threadIdx.x;
    float hloc[CH], cA[CH];
    float a = 1.f, hv = 0.f;
    int s0 = t * CH;
    #pragma unroll
    for (int j = 0; j < CH; j++) {
        int r = b*Ss + s0 + j;
        float dt = g_dt[r*Hh + h];
        float dA = expf(dt * Ah);
        float u  = dt * g_xin[r*Hh + h] * g_p[(size_t)r*TOT + 2*DI + Hh + h*Nn + n];
        hv = dA * hv + u;
        a *= dA;
        hloc[j] = hv; cA[j] = a;
    }
    __shared__ float sA[256], sB[256];
    sA[t] = a; sB[t] = hv;
    __syncthreads();
    for (int off = 1; off < 256; off <<= 1) {
        float pa = 0.f, pb = 0.f;
        if (t >= off) { pa = sA[t - off]; pb = sB[t - off]; }
        __syncthreads();
        if (t >= off) { sB[t] = sA[t] * pb + sB[t]; sA[t] = sA[t] * pa; }
        __syncthreads();
    }
    float hin = (t == 0) ? 0.f : sB[t - 1];
    #pragma unroll
    for (int j = 0; j < CH; j++) {
        int r = b*Ss + s0 + j;
        g_hs[((size_t)r*Hh + h) * Nn + n] = hloc[j] + cA[j] * hin;
    }
}

// ---------------- fused y-reduction + y_proj + gate -> fp16 A operand ----------------
// one block (256 thr) per row: warp w reduces y[w] = sum_n hs*C over 16 lanes,
// then all threads gate 4 channels each.
__global__ __launch_bounds__(256)
void k_yredmix(const float* __restrict__ yw) {
    __shared__ float ys[Hh];
    int r = blockIdx.x;
    int wid = threadIdx.x >> 5, lane = threadIdx.x & 31;

    float v = 0.f;
    if (lane < Nn) {
        v = g_hs[((size_t)r*Hh + wid) * Nn + lane]
          * g_p[(size_t)r*TOT + 2*DI + Hh + Hh*Nn + wid*Nn + lane];
    }
    #pragma unroll
    for (int o = 8; o > 0; o >>= 1) v += __shfl_xor_sync(0xffffffffu, v, o);
    if (lane == 0) ys[wid] = v;
    __syncthreads();

    float y0 = ys[0], y1 = ys[1], y2 = ys[2], y3 = ys[3];
    float y4 = ys[4], y5 = ys[5], y6 = ys[6], y7 = ys[7];

    #pragma unroll
    for (int j = 0; j < 4; j++) {
        int c = threadIdx.x + j * 256;        // 0..1023
        float4 w0 = ((const float4*)yw)[c*2];
        float4 w1 = ((const float4*)yw)[c*2 + 1];
        float s = y0*w0.x + y1*w0.y + y2*w0.z + y3*w0.w
                + y4*w1.x + y5*w1.y + y6*w1.z + y7*w1.w;
        float z = g_p[(size_t)r*TOT + c];
        g_af16[(size_t)r*DI + c] = __float2half_rn(s * siluf(z));
    }
}

// ---------------- final layernorm -> fp16 A operand ----------------
__global__ void k_ln(const float* __restrict__ ln_w, const float* __restrict__ ln_b) {
    __shared__ float sh[256];
    int r = blockIdx.x, t = threadIdx.x;
    float v0 = g_x[(size_t)r*Dd + t];
    float v1 = g_x[(size_t)r*Dd + t + 256];
    float mu = blockReduceSum256(v0 + v1, sh) / (float)Dd;
    float d0 = v0 - mu, d1 = v1 - mu;
    float var = blockReduceSum256(d0*d0 + d1*d1, sh) / (float)Dd;
    float sc = rsqrtf(var + 1e-5f);
    g_af16[(size_t)r*Dd + t]       = __float2half_rn(d0 * sc * ln_w[t]       + ln_b[t]);
    g_af16[(size_t)r*Dd + t + 256] = __float2half_rn(d1 * sc * ln_w[t + 256] + ln_b[t + 256]);
}

// ---------------- launch ----------------
extern "C" void kernel_launch(void* const* d_in, const int* in_sizes, int n_in,
                              void* d_out, int out_size) {
    const int*   tok    = (const int*)  d_in[0];
    const float* emb    = (const float*)d_in[1];
    const float* rms_w  = (const float*)d_in[2];
    const float* in_w   = (const float*)d_in[3];
    const float* conv_w = (const float*)d_in[4];
    const float* dt_b   = (const float*)d_in[5];
    const float* A_log  = (const float*)d_in[6];
    const float* y_w    = (const float*)d_in[7];
    const float* out_w  = (const float*)d_in[8];
    const float* ln_w   = (const float*)d_in[9];
    const float* ln_b   = (const float*)d_in[10];
    const float* head_w = (const float*)d_in[11];
    const float* head_b = (const float*)d_in[12];
    float* out = (float*)d_out;

    float *p_x, *p_p;
    cudaGetSymbolAddress((void**)&p_x, g_x);
    cudaGetSymbolAddress((void**)&p_p, g_p);
    __half *p_a, *p_w;
    cudaGetSymbolAddress((void**)&p_a, g_af16);
    cudaGetSymbolAddress((void**)&p_w, g_wf16);

    static int smem_set = 0;
    if (!smem_set) {
        cudaFuncSetAttribute(k_gemm_fp16<0,0>, cudaFuncAttributeMaxDynamicSharedMemorySize, GEMM_SMEM);
        cudaFuncSetAttribute(k_gemm_fp16<1,0>, cudaFuncAttributeMaxDynamicSharedMemorySize, GEMM_SMEM);
        cudaFuncSetAttribute(k_gemm_fp16<0,1>, cudaFuncAttributeMaxDynamicSharedMemorySize, GEMM_SMEM);
        smem_set = 1;
    }

    // batched weight conversion (all layers + head) up front
    k_wcvt<<<(NLAYERS*TOT*Dd/4 + 255)/256, 256>>>(in_w,  p_w + WOFF_IN,  NLAYERS*TOT*Dd);
    k_wcvt<<<(NLAYERS*Dd*DI/4 + 255)/256, 256>>>(out_w, p_w + WOFF_OUT, NLAYERS*Dd*DI);
    k_wcvt<<<((int)((size_t)Vv*Dd/4) + 255)/256, 256>>>(head_w, p_w + WOFF_HEAD, Vv*Dd);

    k_embed<<<(ROWS*Dd + 255)/256, 256>>>(tok, emb);

    for (int L = 0; L < NLAYERS; L++) {
        k_rms<<<ROWS, 256>>>(rms_w + (size_t)L*Dd);

        // p = xn @ in_w^T  (M=4096, N=2312, K=512)
        {
            dim3 g((TOT + 127)/128, ROWS/128);
            k_gemm_fp16<0,0><<<g, 256, GEMM_SMEM>>>(p_a, p_w + WOFF_IN + (size_t)L*TOT*Dd,
                                                    nullptr, nullptr, p_p, TOT, Dd);
        }

        k_convdtx<<<ROWS, 256>>>(conv_w + (size_t)L*DI*Kk, dt_b + (size_t)L*Hh);
        k_scan<<<Bb*Hh*Nn, 256>>>(A_log + (size_t)L*Hh);
        k_yredmix<<<ROWS, 256>>>(y_w + (size_t)L*DI*Hh);

        // x = yi @ out_w^T + x  (M=4096, N=512, K=1024)
        {
            dim3 g(Dd/128, ROWS/128);
            k_gemm_fp16<1,0><<<g, 256, GEMM_SMEM>>>(p_a, p_w + WOFF_OUT + (size_t)L*Dd*DI,
                                                    p_x, nullptr, p_x, Dd, DI);
        }
    }

    k_ln<<<ROWS, 256>>>(ln_w, ln_b);

    // out = xn @ head_w^T + head_b  (M=4096, N=32000, K=512)
    {
        dim3 g(Vv/128, ROWS/128);
        k_gemm_fp16<0,1><<<g, 256, GEMM_SMEM>>>(p_a, p_w + WOFF_HEAD,
                                                nullptr, head_b, out, Vv, Dd);
    }
}

// round 17
// speedup vs baseline: 1.0849x; 1.0192x over previous
#include <cuda_runtime.h>
#include <cuda_fp16.h>
#include <math.h>
#include <stdint.h>

// ---------------- problem constants ----------------
#define Bb 2
#define Ss 2048
#define Dd 512
#define NLAYERS 6
#define DI 1024
#define Hh 8
#define Nn 16
#define Kk 4
#define Vv 32000
#define TOT (2*DI + Hh + 2*Hh*Nn)   // 2312
#define ROWS (Bb*Ss)                // 4096

// weight pool offsets (halves)
#define WOFF_IN   0
#define WOFF_OUT  (NLAYERS*TOT*Dd)
#define WOFF_HEAD (WOFF_OUT + NLAYERS*Dd*DI)
#define WPOOL     (WOFF_HEAD + (size_t)Vv*Dd)

// ---------------- scratch (static device globals; no allocation) ----------------
__device__ float g_x [ROWS*Dd];
__device__ float g_p [ROWS*TOT];
__device__ float g_dt[ROWS*Hh];
__device__ float g_xin[ROWS*Hh];
__device__ float g_hs[ROWS*Hh*Nn];
__device__ __align__(128) __half g_af16[ROWS*DI];
__device__ __align__(128) __half g_wf16[WPOOL];

// ---------------- small helpers ----------------
__device__ __forceinline__ float blockReduceSum256(float v, float* sh) {
    int t = threadIdx.x;
    sh[t] = v; __syncthreads();
    #pragma unroll
    for (int o = 128; o > 0; o >>= 1) {
        if (t < o) sh[t] += sh[t + o];
        __syncthreads();
    }
    float r = sh[0];
    __syncthreads();
    return r;
}
__device__ __forceinline__ float siluf(float v) { return v / (1.f + expf(-v)); }
__device__ __forceinline__ float softplusf(float v) {
    return (v > 0.f) ? (v + log1pf(expf(-v))) : log1pf(expf(v));
}

// ---------------- MMA primitives (arch-neutral, sm_80+) ----------------
__device__ __forceinline__ void cp16(uint32_t s, const void* g, uint32_t sz) {
    asm volatile("cp.async.cg.shared.global [%0], [%1], 16, %2;"
                 :: "r"(s), "l"(g), "r"(sz) : "memory");
}
__device__ __forceinline__ void cp_commit() {
    asm volatile("cp.async.commit_group;" ::: "memory");
}
__device__ __forceinline__ void cp_wait1() {
    asm volatile("cp.async.wait_group 1;" ::: "memory");
}
__device__ __forceinline__ void ldm4(uint32_t* r, uint32_t a) {
    asm volatile("ldmatrix.sync.aligned.m8n8.x4.shared.b16 {%0,%1,%2,%3}, [%4];"
                 : "=r"(r[0]), "=r"(r[1]), "=r"(r[2]), "=r"(r[3]) : "r"(a));
}
__device__ __forceinline__ void mma16816(float* d, const uint32_t* a,
                                         uint32_t b0, uint32_t b1) {
    asm volatile("mma.sync.aligned.m16n8k16.row.col.f32.f16.f16.f32 "
                 "{%0,%1,%2,%3}, {%4,%5,%6,%7}, {%8,%9}, {%0,%1,%2,%3};"
                 : "+f"(d[0]), "+f"(d[1]), "+f"(d[2]), "+f"(d[3])
                 : "r"(a[0]), "r"(a[1]), "r"(a[2]), "r"(a[3]), "r"(b0), "r"(b1));
}

// ---------------- fp32 -> fp16 weight convert ----------------
__global__ void k_wcvt(const float* __restrict__ src, __half* __restrict__ dst, int n) {
    int i = (blockIdx.x * blockDim.x + threadIdx.x) * 4;
    if (i >= n) return;
    float4 v = *(const float4*)(src + i);
    ((__half2*)(dst + i))[0] = __floats2half2_rn(v.x, v.y);
    ((__half2*)(dst + i))[1] = __floats2half2_rn(v.z, v.w);
}

// ---------------- FP16 GEMM: C[M,N] = A[M,K] @ B[N,K]^T (+res)(+bias) ----------------
// BM=128, BN=128, BK=64. 128 threads = 4 warps, warp tile 64x64 (2x2 warp grid).
// Halves ldmatrix traffic vs 8x(64x32) (smem-BW was the binding pipe).
// 3-stage cp.async pipeline, one barrier per chunk, 2 CTAs/SM.
#define HSTRIDE 144                    // bytes per smem row (128 data + 16 pad)
#define BTILE_H (128*HSTRIDE)          // 18432
#define STAGE_H (2*BTILE_H)            // 36864
#define GEMM_SMEM (3*STAGE_H)          // 110592

template<int ADD_RES, int ADD_BIAS>
__global__ void __launch_bounds__(128, 2)
k_gemm_fp16(const __half* __restrict__ A, const __half* __restrict__ B,
            const float* __restrict__ Res, const float* __restrict__ bias,
            float* __restrict__ C, int Nd, int Kd)
{
    extern __shared__ char smem[];
    const uint32_t sbase = (uint32_t)__cvta_generic_to_shared(smem);

    int tid = threadIdx.x, wid = tid >> 5, lane = tid & 31;
    int bm = blockIdx.y * 128, bn = blockIdx.x * 128;
    int wm = (wid >> 1) * 64, wn = (wid & 1) * 64;

    float acc[4][8][4];                // [m16 tile][n8 tile][frag]
    #pragma unroll
    for (int i = 0; i < 4; i++)
        #pragma unroll
        for (int j = 0; j < 8; j++)
            #pragma unroll
            for (int q = 0; q < 4; q++) acc[i][j][q] = 0.f;

    const int nch = Kd >> 6;

    auto load_stage = [&](int slot, int ch) {
        uint32_t sb = sbase + slot * STAGE_H;
        int k0 = ch << 6;
        // A: 128 rows x 8 chunks of 16B = 1024 cp over 128 threads
        #pragma unroll
        for (int j = 0; j < 8; j++) {
            int c = tid + j * 128;
            int row = c >> 3, q = c & 7;
            uint32_t so = (uint32_t)(row * HSTRIDE + q * 16);
            size_t ga = (size_t)(bm + row) * Kd + k0 + q * 8;
            cp16(sb + so, A + ga, 16);
        }
        // B: 128 rows x 8 chunks
        #pragma unroll
        for (int j = 0; j < 8; j++) {
            int c = tid + j * 128;
            int row = c >> 3, q = c & 7;
            uint32_t so = (uint32_t)(row * HSTRIDE + q * 16);
            int brow = bn + row;
            uint32_t sz = (brow < Nd) ? 16u : 0u;
            int brc = brow < Nd ? brow : (Nd - 1);
            size_t gb = (size_t)brc * Kd + k0 + q * 8;
            cp16(sb + BTILE_H + so, B + gb, sz);
        }
        cp_commit();
    };

    load_stage(0, 0);
    if (nch > 1) load_stage(1, 1); else cp_commit();

    for (int ch = 0; ch < nch; ch++) {
        cp_wait1();
        __syncthreads();
        if (ch + 2 < nch) load_stage((ch + 2) % 3, ch + 2);
        else              cp_commit();

        uint32_t sb = sbase + (ch % 3) * STAGE_H;
        uint32_t sA = sb, sB = sb + BTILE_H;

        #pragma unroll
        for (int ks = 0; ks < 4; ks++) {
            // B fragments for all 4 n16 subtiles of the 64-wide warp tile
            uint32_t bF[4][4];
            int brow = ((lane & 16) ? 8 : 0) + (lane & 7);
            int bcb  = ks * 32 + ((lane & 8) ? 16 : 0);
            #pragma unroll
            for (int nt16 = 0; nt16 < 4; nt16++) {
                uint32_t bo = (uint32_t)((wn + nt16*16 + brow) * HSTRIDE + bcb);
                ldm4(bF[nt16], sB + bo);
            }
            // stream A fragments per 16-row subtile
            int arow = (lane & 15);
            int acb  = ks * 32 + ((lane & 16) ? 16 : 0);
            #pragma unroll
            for (int mt = 0; mt < 4; mt++) {
                uint32_t aF[4];
                uint32_t ao = (uint32_t)((wm + mt*16 + arow) * HSTRIDE + acb);
                ldm4(aF, sA + ao);
                #pragma unroll
                for (int nt16 = 0; nt16 < 4; nt16++) {
                    mma16816(acc[mt][nt16*2],   aF, bF[nt16][0], bF[nt16][1]);
                    mma16816(acc[mt][nt16*2+1], aF, bF[nt16][2], bF[nt16][3]);
                }
            }
        }
    }

    #pragma unroll
    for (int mt = 0; mt < 4; mt++) {
        int r0 = bm + wm + mt*16 + (lane >> 2);
        #pragma unroll
        for (int nt = 0; nt < 8; nt++) {
            int n = bn + wn + nt*8 + (lane & 3) * 2;
            if (n < Nd) {
                float2 v0 = make_float2(acc[mt][nt][0], acc[mt][nt][1]);
                float2 v1 = make_float2(acc[mt][nt][2], acc[mt][nt][3]);
                if (ADD_BIAS) {
                    float2 bv = *(const float2*)(bias + n);
                    v0.x += bv.x; v0.y += bv.y; v1.x += bv.x; v1.y += bv.y;
                }
                if (ADD_RES) {
                    float2 r0v = *(const float2*)(Res + (size_t)r0 * Nd + n);
                    float2 r1v = *(const float2*)(Res + (size_t)(r0+8) * Nd + n);
                    v0.x += r0v.x; v0.y += r0v.y; v1.x += r1v.x; v1.y += r1v.y;
                }
                *(float2*)(C + (size_t)r0 * Nd + n)     = v0;
                *(float2*)(C + (size_t)(r0+8) * Nd + n) = v1;
            }
        }
    }
}

// ---------------- embedding gather ----------------
__global__ void k_embed(const int* __restrict__ tok, const float* __restrict__ emb) {
    int i = blockIdx.x * blockDim.x + threadIdx.x;
    if (i < ROWS * Dd) {
        int r = i / Dd, d = i - r * Dd;
        g_x[i] = emb[(size_t)tok[r] * Dd + d];
    }
}

// ---------------- rmsnorm -> fp16 A operand ----------------
__global__ void k_rms(const float* __restrict__ rms_w) {
    __shared__ float sh[256];
    int r = blockIdx.x, t = threadIdx.x;
    float v0 = g_x[(size_t)r*Dd + t];
    float v1 = g_x[(size_t)r*Dd + t + 256];
    float ss = blockReduceSum256(v0*v0 + v1*v1, sh);
    float sc = rsqrtf(ss / (float)Dd + 1e-6f);
    g_af16[(size_t)r*Dd + t]       = __float2half_rn(v0 * sc * rms_w[t]);
    g_af16[(size_t)r*Dd + t + 256] = __float2half_rn(v1 * sc * rms_w[t + 256]);
}

// ---------------- fused conv+SiLU+head-mean+dt-softplus ----------------
__global__ __launch_bounds__(256)
void k_convdtx(const float* __restrict__ cw, const float* __restrict__ dtb) {
    int r = blockIdx.x;
    int s = r % Ss, b = r / Ss;
    int w = threadIdx.x >> 5, lane = threadIdx.x & 31;
    float sum = 0.f;
    #pragma unroll
    for (int j = 0; j < 4; j++) {
        int c = w * 128 + lane + 32 * j;
        float4 cv = ((const float4*)cw)[c];
        float acc = 0.f;
        const float* base = &g_p[(size_t)(b*Ss) * TOT + DI + c];
        if (s >= 3) {
            acc = base[(size_t)(s-3)*TOT] * cv.x + base[(size_t)(s-2)*TOT] * cv.y
                + base[(size_t)(s-1)*TOT] * cv.z + base[(size_t)s*TOT] * cv.w;
        } else {
            #pragma unroll
            for (int k = 0; k < 4; k++) {
                int sp = s + k - 3;
                if (sp >= 0) acc += base[(size_t)sp*TOT] * ((const float*)&cv)[k];
            }
        }
        sum += siluf(acc);
    }
    #pragma unroll
    for (int o = 16; o > 0; o >>= 1) sum += __shfl_xor_sync(0xffffffffu, sum, o);
    if (lane == 0) {
        g_xin[r*Hh + w] = sum * (1.f / 128.f);
        float dt = g_p[(size_t)r*TOT + 2*DI + w] + dtb[w];
        g_dt[r*Hh + w] = softplusf(dt);
    }
}

// ---------------- parallel associative scan ----------------
__global__ __launch_bounds__(256)
void k_scan(const float* __restrict__ A_log) {
    const int CH = Ss / 256;
    int chain = blockIdx.x;
    int n = chain % Nn;
    int h = (chain / Nn) % Hh;
    int b = chain / (Nn * Hh);
    float Ah = -expf(A_log[h]);

    int t = threadIdx.x;
    float hloc[CH], cA[CH];
    float a = 1.f, hv = 0.f;
    int s0 = t * CH;
    #pragma unroll
    for (int j = 0; j < CH; j++) {
        int r = b*Ss + s0 + j;
        float dt = g_dt[r*Hh + h];
        float dA = expf(dt * Ah);
        float u  = dt * g_xin[r*Hh + h] * g_p[(size_t)r*TOT + 2*DI + Hh + h*Nn + n];
        hv = dA * hv + u;
        a *= dA;
        hloc[j] = hv; cA[j] = a;
    }
    __shared__ float sA[256], sB[256];
    sA[t] = a; sB[t] = hv;
    __syncthreads();
    for (int off = 1; off < 256; off <<= 1) {
        float pa = 0.f, pb = 0.f;
        if (t >= off) { pa = sA[t - off]; pb = sB[t - off]; }
        __syncthreads();
        if (t >= off) { sB[t] = sA[t] * pb + sB[t]; sA[t] = sA[t] * pa; }
        __syncthreads();
    }
    float hin = (t == 0) ? 0.f : sB[t - 1];
    #pragma unroll
    for (int j = 0; j < CH; j++) {
        int r = b*Ss + s0 + j;
        g_hs[((size_t)r*Hh + h) * Nn + n] = hloc[j] + cA[j] * hin;
    }
}

// ---------------- fused y-reduction + y_proj + gate -> fp16 A operand ----------------
__global__ __launch_bounds__(256)
void k_yredmix(const float* __restrict__ yw) {
    __shared__ float ys[Hh];
    int r = blockIdx.x;
    int wid = threadIdx.x >> 5, lane = threadIdx.x & 31;

    float v = 0.f;
    if (lane < Nn) {
        v = g_hs[((size_t)r*Hh + wid) * Nn + lane]
          * g_p[(size_t)r*TOT + 2*DI + Hh + Hh*Nn + wid*Nn + lane];
    }
    #pragma unroll
    for (int o = 8; o > 0; o >>= 1) v += __shfl_xor_sync(0xffffffffu, v, o);
    if (lane == 0) ys[wid] = v;
    __syncthreads();

    float y0 = ys[0], y1 = ys[1], y2 = ys[2], y3 = ys[3];
    float y4 = ys[4], y5 = ys[5], y6 = ys[6], y7 = ys[7];

    #pragma unroll
    for (int j = 0; j < 4; j++) {
        int c = threadIdx.x + j * 256;
        float4 w0 = ((const float4*)yw)[c*2];
        float4 w1 = ((const float4*)yw)[c*2 + 1];
        float s = y0*w0.x + y1*w0.y + y2*w0.z + y3*w0.w
                + y4*w1.x + y5*w1.y + y6*w1.z + y7*w1.w;
        float z = g_p[(size_t)r*TOT + c];
        g_af16[(size_t)r*DI + c] = __float2half_rn(s * siluf(z));
    }
}

// ---------------- final layernorm -> fp16 A operand ----------------
__global__ void k_ln(const float* __restrict__ ln_w, const float* __restrict__ ln_b) {
    __shared__ float sh[256];
    int r = blockIdx.x, t = threadIdx.x;
    float v0 = g_x[(size_t)r*Dd + t];
    float v1 = g_x[(size_t)r*Dd + t + 256];
    float mu = blockReduceSum256(v0 + v1, sh) / (float)Dd;
    float d0 = v0 - mu, d1 = v1 - mu;
    float var = blockReduceSum256(d0*d0 + d1*d1, sh) / (float)Dd;
    float sc = rsqrtf(var + 1e-5f);
    g_af16[(size_t)r*Dd + t]       = __float2half_rn(d0 * sc * ln_w[t]       + ln_b[t]);
    g_af16[(size_t)r*Dd + t + 256] = __float2half_rn(d1 * sc * ln_w[t + 256] + ln_b[t + 256]);
}

// ---------------- launch ----------------
extern "C" void kernel_launch(void* const* d_in, const int* in_sizes, int n_in,
                              void* d_out, int out_size) {
    const int*   tok    = (const int*)  d_in[0];
    const float* emb    = (const float*)d_in[1];
    const float* rms_w  = (const float*)d_in[2];
    const float* in_w   = (const float*)d_in[3];
    const float* conv_w = (const float*)d_in[4];
    const float* dt_b   = (const float*)d_in[5];
    const float* A_log  = (const float*)d_in[6];
    const float* y_w    = (const float*)d_in[7];
    const float* out_w  = (const float*)d_in[8];
    const float* ln_w   = (const float*)d_in[9];
    const float* ln_b   = (const float*)d_in[10];
    const float* head_w = (const float*)d_in[11];
    const float* head_b = (const float*)d_in[12];
    float* out = (float*)d_out;

    float *p_x, *p_p;
    cudaGetSymbolAddress((void**)&p_x, g_x);
    cudaGetSymbolAddress((void**)&p_p, g_p);
    __half *p_a, *p_w;
    cudaGetSymbolAddress((void**)&p_a, g_af16);
    cudaGetSymbolAddress((void**)&p_w, g_wf16);

    static int smem_set = 0;
    if (!smem_set) {
        cudaFuncSetAttribute(k_gemm_fp16<0,0>, cudaFuncAttributeMaxDynamicSharedMemorySize, GEMM_SMEM);
        cudaFuncSetAttribute(k_gemm_fp16<1,0>, cudaFuncAttributeMaxDynamicSharedMemorySize, GEMM_SMEM);
        cudaFuncSetAttribute(k_gemm_fp16<0,1>, cudaFuncAttributeMaxDynamicSharedMemorySize, GEMM_SMEM);
        smem_set = 1;
    }

    // batched weight conversion (all layers + head) up front
    k_wcvt<<<(NLAYERS*TOT*Dd/4 + 255)/256, 256>>>(in_w,  p_w + WOFF_IN,  NLAYERS*TOT*Dd);
    k_wcvt<<<(NLAYERS*Dd*DI/4 + 255)/256, 256>>>(out_w, p_w + WOFF_OUT, NLAYERS*Dd*DI);
    k_wcvt<<<((int)((size_t)Vv*Dd/4) + 255)/256, 256>>>(head_w, p_w + WOFF_HEAD, Vv*Dd);

    k_embed<<<(ROWS*Dd + 255)/256, 256>>>(tok, emb);

    for (int L = 0; L < NLAYERS; L++) {
        k_rms<<<ROWS, 256>>>(rms_w + (size_t)L*Dd);

        // p = xn @ in_w^T  (M=4096, N=2312, K=512)
        {
            dim3 g((TOT + 127)/128, ROWS/128);
            k_gemm_fp16<0,0><<<g, 128, GEMM_SMEM>>>(p_a, p_w + WOFF_IN + (size_t)L*TOT*Dd,
                                                    nullptr, nullptr, p_p, TOT, Dd);
        }

        k_convdtx<<<ROWS, 256>>>(conv_w + (size_t)L*DI*Kk, dt_b + (size_t)L*Hh);
        k_scan<<<Bb*Hh*Nn, 256>>>(A_log + (size_t)L*Hh);
        k_yredmix<<<ROWS, 256>>>(y_w + (size_t)L*DI*Hh);

        // x = yi @ out_w^T + x  (M=4096, N=512, K=1024)
        {
            dim3 g(Dd/128, ROWS/128);
            k_gemm_fp16<1,0><<<g, 128, GEMM_SMEM>>>(p_a, p_w + WOFF_OUT + (size_t)L*Dd*DI,
                                                    p_x, nullptr, p_x, Dd, DI);
        }
    }

    k_ln<<<ROWS, 256>>>(ln_w, ln_b);

    // out = xn @ head_w^T + head_b  (M=4096, N=32000, K=512)
    {
        dim3 g(Vv/128, ROWS/128);
        k_gemm_fp16<0,1><<<g, 128, GEMM_SMEM>>>(p_a, p_w + WOFF_HEAD,
                                                nullptr, head_b, out, Vv, Dd);
    }
}